// round 1
// baseline (speedup 1.0000x reference)
#include <cuda_runtime.h>
#include <cuda_bf16.h>

#define Bn 64
#define Ln 256
#define Vn 256
#define En 256
#define Hn 1024
#define NG3 3072          // 3*H
#define NB 147            // persistent blocks (<= SM count, all resident)
#define NJ 7              // hidden columns per block (147*7 >= 1024)
#define NC 21             // 3 gates * NJ
#define HB (Hn*Bn)        // 65536 floats per timestep slab

// -------- static device scratch (no allocations allowed) --------
__device__ float g_EW[Vn*NG3];          // embedding @ Wi (+bh for r,z gates)   3 MB
__device__ float g_WhT[NG3*Hn];         // Wh transposed: WhT[n][k]            12.6 MB
__device__ float g_YH[(Ln+1)*HB];       // h history, transposed [t][j][b]     67.4 MB
__device__ int   g_arrive[256];
__device__ int   g_go;

// =================== reset (barrier flags + h0 = 0) ===================
__global__ void reset_kernel() {
    int tid = blockIdx.x * blockDim.x + threadIdx.x;
    for (int i = tid; i < HB; i += gridDim.x * blockDim.x) g_YH[i] = 0.0f;
    if (blockIdx.x == 0) {
        if (threadIdx.x < 256) g_arrive[threadIdx.x] = 0;
        if (threadIdx.x == 0) g_go = 0;
    }
}

// =================== EW = embedding @ Wi (+ bh folded for r,z) ===================
// grid (24, 8): 128 cols x 32 rows per block
__global__ __launch_bounds__(256) void ew_kernel(const float* __restrict__ emb,
                                                 const float* __restrict__ Wi,
                                                 const float* __restrict__ bh) {
    __shared__ float semb[32][En];   // 32 KB
    int vbase = blockIdx.y * 32;
    int cbase = blockIdx.x * 128;
    int tid = threadIdx.x;
    for (int i = tid; i < 32 * En / 4; i += 256)
        ((float4*)&semb[0][0])[i] = ((const float4*)(emb + (size_t)vbase * En))[i];
    __syncthreads();

    int cq = tid & 31;     // 32 groups of 4 cols
    int vq = tid >> 5;     // 8 groups of 4 rows
    int c  = cbase + cq * 4;
    int v0 = vq * 4;
    float acc[4][4];
    #pragma unroll
    for (int i = 0; i < 4; i++)
        #pragma unroll
        for (int j = 0; j < 4; j++) acc[i][j] = 0.0f;

    for (int e = 0; e < En; e++) {
        float4 w = *(const float4*)(Wi + (size_t)e * NG3 + c);
        #pragma unroll
        for (int vv = 0; vv < 4; vv++) {
            float a = semb[v0 + vv][e];
            acc[vv][0] = fmaf(a, w.x, acc[vv][0]);
            acc[vv][1] = fmaf(a, w.y, acc[vv][1]);
            acc[vv][2] = fmaf(a, w.z, acc[vv][2]);
            acc[vv][3] = fmaf(a, w.w, acc[vv][3]);
        }
    }
    // fold bh into r,z gates only (n gate: bias applied inside r*(...) in GRU step)
    float4 bb = make_float4(0.f, 0.f, 0.f, 0.f);
    if (c < 2 * Hn) bb = *(const float4*)(bh + c);
    #pragma unroll
    for (int vv = 0; vv < 4; vv++) {
        float4 o;
        o.x = acc[vv][0] + bb.x; o.y = acc[vv][1] + bb.y;
        o.z = acc[vv][2] + bb.z; o.w = acc[vv][3] + bb.w;
        *(float4*)(g_EW + (size_t)(vbase + v0 + vv) * NG3 + c) = o;
    }
}

// =================== WhT[n][k] = Wh[k][n] ===================
__global__ void transpose_kernel(const float* __restrict__ Wh) {
    __shared__ float tile[32][33];
    int n0 = blockIdx.x * 32, k0 = blockIdx.y * 32;
    int tx = threadIdx.x, ty = threadIdx.y;   // 32 x 8
    #pragma unroll
    for (int i = 0; i < 32; i += 8)
        tile[ty + i][tx] = Wh[(size_t)(k0 + ty + i) * NG3 + n0 + tx];
    __syncthreads();
    #pragma unroll
    for (int i = 0; i < 32; i += 8)
        g_WhT[(size_t)(n0 + ty + i) * Hn + k0 + tx] = tile[tx][ty + i];
}

// =================== persistent GRU recurrence ===================
// 147 blocks x 256 threads. Block owns hidden cols [j0, j0+nj).
// SMEM: ws[21][1024] (Wh slice, loaded ONCE) + red[16][64][21] partial sums.
extern __shared__ float smem_gru[];

__global__ __launch_bounds__(256, 1) void gru_kernel(const int* __restrict__ tokens,
                                                     const float* __restrict__ bh) {
    float* ws  = smem_gru;              // NC * Hn floats
    float* red = smem_gru + NC * Hn;    // 16 * Bn * NC floats
    __shared__ int stok[Bn];

    int tid = threadIdx.x, bid = blockIdx.x;
    int j0 = bid * NJ;
    int nj = Hn - j0; if (nj > NJ) nj = NJ;

    // Load Wh slice once; zero-pad tail block's unused rows.
    for (int idx = tid; idx < NC * Hn; idx += 256) {
        int c = idx >> 10, k = idx & (Hn - 1);
        int gg = c / NJ, jj = c - gg * NJ;
        float w = 0.0f;
        if (jj < nj) w = g_WhT[(size_t)(gg * Hn + j0 + jj) * Hn + k];
        ws[idx] = w;
    }
    __syncthreads();

    int bq = tid & 15, kq = tid >> 4;   // 16 b-groups x 16 k-groups
    int k0 = kq * 64;
    int bb = bq * 4;

    for (int t = 0; t < Ln; t++) {
        const float* hbase = g_YH + (size_t)t * HB;

        // --- Phase A: partial GEMM over this thread's 64-k slice ---
        float acc[NC][4];
        #pragma unroll
        for (int c = 0; c < NC; c++) {
            acc[c][0] = 0.f; acc[c][1] = 0.f; acc[c][2] = 0.f; acc[c][3] = 0.f;
        }
        #pragma unroll 1
        for (int kk = 0; kk < 64; kk += 4) {
            int k = k0 + kk;
            float4 h0 = *(const float4*)(hbase + (size_t)(k + 0) * Bn + bb);
            float4 h1 = *(const float4*)(hbase + (size_t)(k + 1) * Bn + bb);
            float4 h2 = *(const float4*)(hbase + (size_t)(k + 2) * Bn + bb);
            float4 h3 = *(const float4*)(hbase + (size_t)(k + 3) * Bn + bb);
            #pragma unroll
            for (int c = 0; c < NC; c++) {
                float4 w = *(const float4*)(ws + c * Hn + k);
                acc[c][0] = fmaf(h0.x, w.x, acc[c][0]);
                acc[c][1] = fmaf(h0.y, w.x, acc[c][1]);
                acc[c][2] = fmaf(h0.z, w.x, acc[c][2]);
                acc[c][3] = fmaf(h0.w, w.x, acc[c][3]);
                acc[c][0] = fmaf(h1.x, w.y, acc[c][0]);
                acc[c][1] = fmaf(h1.y, w.y, acc[c][1]);
                acc[c][2] = fmaf(h1.z, w.y, acc[c][2]);
                acc[c][3] = fmaf(h1.w, w.y, acc[c][3]);
                acc[c][0] = fmaf(h2.x, w.z, acc[c][0]);
                acc[c][1] = fmaf(h2.y, w.z, acc[c][1]);
                acc[c][2] = fmaf(h2.z, w.z, acc[c][2]);
                acc[c][3] = fmaf(h2.w, w.z, acc[c][3]);
                acc[c][0] = fmaf(h3.x, w.w, acc[c][0]);
                acc[c][1] = fmaf(h3.y, w.w, acc[c][1]);
                acc[c][2] = fmaf(h3.z, w.w, acc[c][2]);
                acc[c][3] = fmaf(h3.w, w.w, acc[c][3]);
            }
        }

        // --- Phase B: stash partials, fetch this step's tokens ---
        #pragma unroll
        for (int c = 0; c < NC; c++) {
            #pragma unroll
            for (int i = 0; i < 4; i++)
                red[(kq * Bn + bb + i) * NC + c] = acc[c][i];
        }
        if (tid < Bn) stok[tid] = tokens[tid * Ln + t];
        __syncthreads();

        // --- Phase C: reduce 16 K-partials, apply gates, write h_{t+1} ---
        for (int o = tid; o < Bn * NJ; o += 256) {
            int b = o & (Bn - 1), jj = o >> 6;
            if (jj < nj) {
                float s0 = 0.f, s1 = 0.f, s2 = 0.f;
                #pragma unroll
                for (int q = 0; q < 16; q++) {
                    const float* rp = red + (q * Bn + b) * NC;
                    s0 += rp[0 * NJ + jj];
                    s1 += rp[1 * NJ + jj];
                    s2 += rp[2 * NJ + jj];
                }
                int j = j0 + jj;
                const float* ew = g_EW + (size_t)stok[b] * NG3;
                float xr = ew[j], xz = ew[Hn + j], xn = ew[2 * Hn + j];
                float r = 1.0f / (1.0f + __expf(-(xr + s0)));
                float z = 1.0f / (1.0f + __expf(-(xz + s1)));
                float hnl = s2 + bh[2 * Hn + j];
                float n = tanhf(xn + r * hnl);
                float hp = hbase[(size_t)j * Bn + b];
                float hnew = (1.0f - z) * n + z * hp;
                g_YH[(size_t)(t + 1) * HB + (size_t)j * Bn + b] = hnew;
            }
        }

        // --- grid barrier ---
        __syncthreads();
        if (tid == 0) {
            __threadfence();
            ((volatile int*)g_arrive)[bid] = t + 1;
        }
        if (bid == 0) {
            if (tid < NB) {
                while (((volatile int*)g_arrive)[tid] < t + 1) { }
            }
            __syncthreads();
            if (tid == 0) {
                __threadfence();
                *(volatile int*)&g_go = t + 1;
            }
        }
        if (tid == 0) {
            while (*(volatile int*)&g_go < t + 1) { }
            __threadfence();
        }
        __syncthreads();
    }
}

// =================== logits = Y @ Wout + bout ===================
// grid (2, 256): block = one timestep x 128-v tile; 64b x 128v, K=1024
__global__ __launch_bounds__(256, 1) void out_kernel(const float* __restrict__ Wout,
                                                     const float* __restrict__ bout,
                                                     float* __restrict__ out) {
    __shared__ float sY[32 * Bn];     // [kk][b]
    __shared__ float sW[32 * 128];    // [kk][v]
    int t = blockIdx.y;
    int vbase = blockIdx.x * 128;
    int tid = threadIdx.x;
    int bq = tid & 15, vq = tid >> 4;
    int bb = bq * 4;
    int vv0 = vq * 8;
    const float* Yt = g_YH + (size_t)(t + 1) * HB;

    float acc[4][8];
    #pragma unroll
    for (int i = 0; i < 4; i++)
        #pragma unroll
        for (int j = 0; j < 8; j++) acc[i][j] = 0.0f;

    for (int kc = 0; kc < Hn; kc += 32) {
        for (int i = tid; i < 32 * Bn / 4; i += 256)
            ((float4*)sY)[i] = ((const float4*)(Yt + (size_t)kc * Bn))[i];
        for (int i = tid; i < 32 * 128 / 4; i += 256) {
            int kk = i >> 5;
            int v4 = (i & 31) * 4;
            ((float4*)sW)[i] = *(const float4*)(Wout + (size_t)(kc + kk) * Vn + vbase + v4);
        }
        __syncthreads();
        #pragma unroll 4
        for (int kk = 0; kk < 32; kk++) {
            float4 y4 = *(const float4*)(sY + kk * Bn + bb);
            float4 wa = *(const float4*)(sW + kk * 128 + vv0);
            float4 wb = *(const float4*)(sW + kk * 128 + vv0 + 4);
            float yv[4] = {y4.x, y4.y, y4.z, y4.w};
            float wv[8] = {wa.x, wa.y, wa.z, wa.w, wb.x, wb.y, wb.z, wb.w};
            #pragma unroll
            for (int i = 0; i < 4; i++)
                #pragma unroll
                for (int j = 0; j < 8; j++)
                    acc[i][j] = fmaf(yv[i], wv[j], acc[i][j]);
        }
        __syncthreads();
    }

    float4 ba = *(const float4*)(bout + vbase + vv0);
    float4 bbv = *(const float4*)(bout + vbase + vv0 + 4);
    float bsum[8] = {ba.x, ba.y, ba.z, ba.w, bbv.x, bbv.y, bbv.z, bbv.w};
    #pragma unroll
    for (int i = 0; i < 4; i++) {
        float* po = out + (size_t)(bb + i) * Ln * Vn + (size_t)t * Vn + vbase + vv0;
        float4 o0, o1;
        o0.x = acc[i][0] + bsum[0]; o0.y = acc[i][1] + bsum[1];
        o0.z = acc[i][2] + bsum[2]; o0.w = acc[i][3] + bsum[3];
        o1.x = acc[i][4] + bsum[4]; o1.y = acc[i][5] + bsum[5];
        o1.z = acc[i][6] + bsum[6]; o1.w = acc[i][7] + bsum[7];
        *(float4*)(po + 0) = o0;
        *(float4*)(po + 4) = o1;
    }
}

// =================== launch ===================
extern "C" void kernel_launch(void* const* d_in, const int* in_sizes, int n_in,
                              void* d_out, int out_size) {
    const int*   tokens = (const int*)d_in[0];
    const float* emb    = (const float*)d_in[1];
    const float* Wi     = (const float*)d_in[2];
    const float* Wh     = (const float*)d_in[3];
    const float* bh     = (const float*)d_in[4];
    const float* Wout   = (const float*)d_in[5];
    const float* bout   = (const float*)d_in[6];
    float* out = (float*)d_out;

    const int smem_bytes = (NC * Hn + 16 * Bn * NC) * (int)sizeof(float); // 172032
    cudaFuncSetAttribute(gru_kernel, cudaFuncAttributeMaxDynamicSharedMemorySize, smem_bytes);

    reset_kernel<<<32, 256>>>();
    ew_kernel<<<dim3(24, 8), 256>>>(emb, Wi, bh);
    transpose_kernel<<<dim3(96, 32), dim3(32, 8)>>>(Wh);
    gru_kernel<<<NB, 256, smem_bytes>>>(tokens, bh);
    out_kernel<<<dim3(2, 256), 256>>>(Wout, bout, out);
}

// round 2
// speedup vs baseline: 1.2009x; 1.2009x over previous
#include <cuda_runtime.h>
#include <cuda_bf16.h>

#define Bn 64
#define Ln 256
#define Vn 256
#define En 256
#define Hn 1024
#define NG3 3072          // 3*H
#define NB 147            // persistent blocks (one per SM, all co-resident)
#define NJ 7              // hidden columns per block (147*7 = 1029 >= 1024)
#define NCr 21            // real columns = 3 gates * NJ
#define NCP 11            // column pairs (21 -> 11 pairs, last half-padded)
#define ROWW 24           // padded ws row width (floats), 96B = 16B aligned
#define CHUNK 45          // per-thread red chunk (u64), padded for bank spread
#define HB (Hn*Bn)        // 65536 floats per timestep slab

typedef unsigned long long u64;

// -------- static device scratch (no allocations allowed) --------
__device__ float g_EW[Vn*NG3];          // embedding @ Wi (+bh for r,z gates)   3 MB
__device__ float g_YH[(Ln+1)*HB];       // h history, [t][j][b]                67.4 MB
__device__ unsigned int g_ctr;

__device__ __forceinline__ u64 fma2(u64 a, u64 b, u64 c) {
    u64 d;
    asm("fma.rn.f32x2 %0, %1, %2, %3;" : "=l"(d) : "l"(a), "l"(b), "l"(c));
    return d;
}
__device__ __forceinline__ u64 pack2(float x) {
    u64 d;
    asm("mov.b64 %0, {%1, %1};" : "=l"(d) : "f"(x));
    return d;
}

// =================== reset (h0 = 0, barrier counter) ===================
__global__ void reset_kernel() {
    int tid = blockIdx.x * blockDim.x + threadIdx.x;
    for (int i = tid; i < HB; i += gridDim.x * blockDim.x) g_YH[i] = 0.0f;
    if (blockIdx.x == 0 && threadIdx.x == 0) g_ctr = 0u;
}

// =================== EW = embedding @ Wi (+ bh folded for r,z) ===================
__global__ __launch_bounds__(256) void ew_kernel(const float* __restrict__ emb,
                                                 const float* __restrict__ Wi,
                                                 const float* __restrict__ bh) {
    __shared__ float semb[32][En];
    int vbase = blockIdx.y * 32;
    int cbase = blockIdx.x * 128;
    int tid = threadIdx.x;
    for (int i = tid; i < 32 * En / 4; i += 256)
        ((float4*)&semb[0][0])[i] = ((const float4*)(emb + (size_t)vbase * En))[i];
    __syncthreads();

    int cq = tid & 31;
    int vq = tid >> 5;
    int c  = cbase + cq * 4;
    int v0 = vq * 4;
    float acc[4][4];
    #pragma unroll
    for (int i = 0; i < 4; i++)
        #pragma unroll
        for (int j = 0; j < 4; j++) acc[i][j] = 0.0f;

    for (int e = 0; e < En; e++) {
        float4 w = *(const float4*)(Wi + (size_t)e * NG3 + c);
        #pragma unroll
        for (int vv = 0; vv < 4; vv++) {
            float a = semb[v0 + vv][e];
            acc[vv][0] = fmaf(a, w.x, acc[vv][0]);
            acc[vv][1] = fmaf(a, w.y, acc[vv][1]);
            acc[vv][2] = fmaf(a, w.z, acc[vv][2]);
            acc[vv][3] = fmaf(a, w.w, acc[vv][3]);
        }
    }
    float4 bb = make_float4(0.f, 0.f, 0.f, 0.f);
    if (c < 2 * Hn) bb = *(const float4*)(bh + c);
    #pragma unroll
    for (int vv = 0; vv < 4; vv++) {
        float4 o;
        o.x = acc[vv][0] + bb.x; o.y = acc[vv][1] + bb.y;
        o.z = acc[vv][2] + bb.z; o.w = acc[vv][3] + bb.w;
        *(float4*)(g_EW + (size_t)(vbase + v0 + vv) * NG3 + c) = o;
    }
}

// =================== persistent GRU recurrence (FFMA2 path) ===================
// 147 blocks x 256 threads. Block owns hidden cols [j0, j0+nj), nj<=7.
// SMEM: ws[1024][24] (Wh slice, k-major, col pairs interleaved, loaded ONCE)
//     + red: 256 thread-private chunks of 45 u64 (K-partial sums).
extern __shared__ float smem_gru[];

__global__ __launch_bounds__(256, 1) void gru_kernel(const int* __restrict__ tokens,
                                                     const float* __restrict__ Wh,
                                                     const float* __restrict__ bh) {
    float* ws = smem_gru;                         // ROWW * Hn floats (98304 B)
    u64*  red = (u64*)(smem_gru + ROWW * Hn);     // 256 * CHUNK u64   (92160 B)
    __shared__ int stok[Bn];

    int tid = threadIdx.x, bid = blockIdx.x;
    int j0 = bid * NJ;
    int nj = Hn - j0; if (nj > NJ) nj = NJ;
    if (nj < 0) nj = 0;

    // Load Wh slice once: ws[k][c], c = gate*7 + jj (cols 21..23 are zero pad).
    for (int idx = tid; idx < ROWW * Hn; idx += 256) {
        int k = idx / ROWW, c = idx - k * ROWW;
        float w = 0.0f;
        if (c < NCr) {
            int g = (c < 7) ? 0 : ((c < 14) ? 1 : 2);
            int jj = c - g * 7;
            if (jj < nj) w = Wh[(size_t)k * NG3 + g * Hn + j0 + jj];
        }
        ws[idx] = w;
    }
    __syncthreads();

    int bq = tid & 15, kq = tid >> 4;   // 16 b-groups x 16 k-groups
    int k0 = kq * 64;
    int bb = bq * 4;
    u64* redt = red + ((size_t)kq * 16 + bq) * CHUNK;

    for (int t = 0; t < Ln; t++) {
        const float* hbase = g_YH + (size_t)t * HB;

        // --- Phase A: partial GEMM over this thread's 64-k slice, f32x2 packed ---
        u64 acc[NCP][4];
        #pragma unroll
        for (int cp = 0; cp < NCP; cp++) {
            acc[cp][0] = 0ull; acc[cp][1] = 0ull; acc[cp][2] = 0ull; acc[cp][3] = 0ull;
        }

        float4 hc[4];
        #pragma unroll
        for (int k = 0; k < 4; k++)
            hc[k] = *(const float4*)(hbase + (size_t)(k0 + k) * Bn + bb);

        #pragma unroll 1
        for (int kk = 0; kk < 64; kk += 4) {
            // prefetch next k-quad (re-load current quad on last iter: harmless)
            int knext = (kk + 4 < 64) ? (kk + 4) : kk;
            float4 hn[4];
            #pragma unroll
            for (int k = 0; k < 4; k++)
                hn[k] = *(const float4*)(hbase + (size_t)(k0 + knext + k) * Bn + bb);

            #pragma unroll
            for (int k = 0; k < 4; k++) {
                const char* wrow = (const char*)(ws + (size_t)(k0 + kk + k) * ROWW);
                ulonglong2 w01 = *(const ulonglong2*)(wrow);
                ulonglong2 w23 = *(const ulonglong2*)(wrow + 16);
                ulonglong2 w45 = *(const ulonglong2*)(wrow + 32);
                ulonglong2 w67 = *(const ulonglong2*)(wrow + 48);
                ulonglong2 w89 = *(const ulonglong2*)(wrow + 64);
                u64       w10 = *(const u64*)(wrow + 80);
                u64 wp[NCP] = {w01.x, w01.y, w23.x, w23.y, w45.x, w45.y,
                               w67.x, w67.y, w89.x, w89.y, w10};
                u64 hh0 = pack2(hc[k].x);
                u64 hh1 = pack2(hc[k].y);
                u64 hh2 = pack2(hc[k].z);
                u64 hh3 = pack2(hc[k].w);
                #pragma unroll
                for (int cp = 0; cp < NCP; cp++) {
                    acc[cp][0] = fma2(wp[cp], hh0, acc[cp][0]);
                    acc[cp][1] = fma2(wp[cp], hh1, acc[cp][1]);
                    acc[cp][2] = fma2(wp[cp], hh2, acc[cp][2]);
                    acc[cp][3] = fma2(wp[cp], hh3, acc[cp][3]);
                }
            }
            #pragma unroll
            for (int k = 0; k < 4; k++) hc[k] = hn[k];
        }

        // --- Phase B: stash packed partials (thread-private chunk, bank-spread) ---
        #pragma unroll
        for (int i = 0; i < 4; i++)
            #pragma unroll
            for (int cp = 0; cp < NCP; cp++)
                redt[i * NCP + cp] = acc[cp][i];
        if (tid < Bn) stok[tid] = tokens[tid * Ln + t];
        __syncthreads();

        // --- Phase C: reduce 16 K-partials, apply gates, write h_{t+1} ---
        const float* rf = (const float*)red;
        for (int o = tid; o < Bn * NJ; o += 256) {
            int b = o & 63, jj = o >> 6;
            if (jj < nj) {
                int bq2 = b >> 2, i2 = b & 3;
                int c0 = jj, c1 = 7 + jj, c2 = 14 + jj;
                float s0 = 0.f, s1 = 0.f, s2 = 0.f;
                #pragma unroll
                for (int q = 0; q < 16; q++) {
                    const float* rp = rf + (((size_t)q * 16 + bq2) * CHUNK + (size_t)i2 * NCP) * 2;
                    s0 += rp[c0];
                    s1 += rp[c1];
                    s2 += rp[c2];
                }
                int j = j0 + jj;
                const float* ew = g_EW + (size_t)stok[b] * NG3;
                float xr = ew[j], xz = ew[Hn + j], xn = ew[2 * Hn + j];
                float r = 1.0f / (1.0f + __expf(-(xr + s0)));
                float z = 1.0f / (1.0f + __expf(-(xz + s1)));
                float hnl = s2 + bh[2 * Hn + j];
                float n = tanhf(xn + r * hnl);
                float hp = hbase[(size_t)j * Bn + b];
                float hnew = (1.0f - z) * n + z * hp;
                g_YH[(size_t)(t + 1) * HB + (size_t)j * Bn + b] = hnew;
            }
        }

        // --- grid barrier (counter-based) ---
        __syncthreads();
        if (tid == 0) {
            __threadfence();
            atomicAdd(&g_ctr, 1u);
            unsigned target = (unsigned)NB * (unsigned)(t + 1);
            while (*((volatile unsigned*)&g_ctr) < target) { }
        }
        __syncthreads();
    }
}

// =================== logits = Y @ Wout + bout (FFMA2) ===================
// grid (2, 256): block = one timestep x 128-v tile; 64b x 128v, K=1024
__global__ __launch_bounds__(256, 1) void out_kernel(const float* __restrict__ Wout,
                                                     const float* __restrict__ bout,
                                                     float* __restrict__ out) {
    __shared__ float sY[32 * Bn];     // [kk][b]
    __shared__ float sW[32 * 128];    // [kk][v]
    int t = blockIdx.y;
    int vbase = blockIdx.x * 128;
    int tid = threadIdx.x;
    int bq = tid & 15, vq = tid >> 4;
    int bb = bq * 4;
    int vv0 = vq * 8;
    const float* Yt = g_YH + (size_t)(t + 1) * HB;

    u64 acc2[4][4];
    #pragma unroll
    for (int i = 0; i < 4; i++)
        #pragma unroll
        for (int j = 0; j < 4; j++) acc2[i][j] = 0ull;

    for (int kc = 0; kc < Hn; kc += 32) {
        for (int i = tid; i < 32 * Bn / 4; i += 256)
            ((float4*)sY)[i] = ((const float4*)(Yt + (size_t)kc * Bn))[i];
        for (int i = tid; i < 32 * 128 / 4; i += 256) {
            int kk = i >> 5;
            int v4 = (i & 31) * 4;
            ((float4*)sW)[i] = *(const float4*)(Wout + (size_t)(kc + kk) * Vn + vbase + v4);
        }
        __syncthreads();
        #pragma unroll 4
        for (int kk = 0; kk < 32; kk++) {
            float4 y4 = *(const float4*)(sY + kk * Bn + bb);
            ulonglong2 wA = *(const ulonglong2*)(sW + kk * 128 + vv0);
            ulonglong2 wB = *(const ulonglong2*)(sW + kk * 128 + vv0 + 4);
            u64 wp[4] = {wA.x, wA.y, wB.x, wB.y};
            u64 yy[4] = {pack2(y4.x), pack2(y4.y), pack2(y4.z), pack2(y4.w)};
            #pragma unroll
            for (int i = 0; i < 4; i++)
                #pragma unroll
                for (int j = 0; j < 4; j++)
                    acc2[i][j] = fma2(yy[i], wp[j], acc2[i][j]);
        }
        __syncthreads();
    }

    float4 ba = *(const float4*)(bout + vbase + vv0);
    float4 bbv = *(const float4*)(bout + vbase + vv0 + 4);
    float bsum[8] = {ba.x, ba.y, ba.z, ba.w, bbv.x, bbv.y, bbv.z, bbv.w};
    #pragma unroll
    for (int i = 0; i < 4; i++) {
        float vals[8];
        #pragma unroll
        for (int j = 0; j < 4; j++) {
            unsigned lo, hi;
            asm("mov.b64 {%0, %1}, %2;" : "=r"(lo), "=r"(hi) : "l"(acc2[i][j]));
            vals[2 * j]     = __uint_as_float(lo);
            vals[2 * j + 1] = __uint_as_float(hi);
        }
        float* po = out + (size_t)(bb + i) * Ln * Vn + (size_t)t * Vn + vbase + vv0;
        float4 o0, o1;
        o0.x = vals[0] + bsum[0]; o0.y = vals[1] + bsum[1];
        o0.z = vals[2] + bsum[2]; o0.w = vals[3] + bsum[3];
        o1.x = vals[4] + bsum[4]; o1.y = vals[5] + bsum[5];
        o1.z = vals[6] + bsum[6]; o1.w = vals[7] + bsum[7];
        *(float4*)(po + 0) = o0;
        *(float4*)(po + 4) = o1;
    }
}

// =================== launch ===================
extern "C" void kernel_launch(void* const* d_in, const int* in_sizes, int n_in,
                              void* d_out, int out_size) {
    const int*   tokens = (const int*)d_in[0];
    const float* emb    = (const float*)d_in[1];
    const float* Wi     = (const float*)d_in[2];
    const float* Wh     = (const float*)d_in[3];
    const float* bh     = (const float*)d_in[4];
    const float* Wout   = (const float*)d_in[5];
    const float* bout   = (const float*)d_in[6];
    float* out = (float*)d_out;

    const int smem_bytes = ROWW * Hn * (int)sizeof(float) + 256 * CHUNK * (int)sizeof(u64);
    cudaFuncSetAttribute(gru_kernel, cudaFuncAttributeMaxDynamicSharedMemorySize, smem_bytes);

    reset_kernel<<<32, 256>>>();
    ew_kernel<<<dim3(24, 8), 256>>>(emb, Wi, bh);
    gru_kernel<<<NB, 256, smem_bytes>>>(tokens, Wh, bh);
    out_kernel<<<dim3(2, 256), 256>>>(Wout, bout, out);
}

// round 3
// speedup vs baseline: 1.2041x; 1.0027x over previous
#include <cuda_runtime.h>
#include <cuda_bf16.h>

#define Bn 64
#define Ln 256
#define Vn 256
#define En 256
#define Hn 1024
#define NG3 3072          // 3*H
#define NB 147            // persistent blocks (one per SM, all co-resident)
#define NJ 7              // hidden columns per block (147*7 = 1029 >= 1024)
#define NCr 21            // real columns = 3 gates * NJ
#define NCP 11            // column pairs (21 -> 11 pairs, last half-padded)
#define ROWW 24           // padded ws row width (floats), 96B = 16B aligned
#define CHUNK 45          // per-thread red chunk (u64), padded for bank spread
#define HB (Hn*Bn)        // 65536 floats per timestep slab

typedef unsigned long long u64;

// -------- static device scratch (no allocations allowed) --------
__device__ float g_EW[Vn*NG3];          // embedding @ Wi (+bh for r,z gates)   3 MB
__device__ float g_YH[(Ln+1)*HB];       // h history, [t][j][b]                67.4 MB
__device__ unsigned int g_ctr;

__device__ __forceinline__ u64 fma2(u64 a, u64 b, u64 c) {
    u64 d;
    asm("fma.rn.f32x2 %0, %1, %2, %3;" : "=l"(d) : "l"(a), "l"(b), "l"(c));
    return d;
}
__device__ __forceinline__ u64 pack2(float x) {
    u64 d;
    asm("mov.b64 %0, {%1, %1};" : "=l"(d) : "f"(x));
    return d;
}

// =================== reset (h0 = 0, barrier counter) ===================
__global__ void reset_kernel() {
    int tid = blockIdx.x * blockDim.x + threadIdx.x;
    for (int i = tid; i < HB; i += gridDim.x * blockDim.x) g_YH[i] = 0.0f;
    if (blockIdx.x == 0 && threadIdx.x == 0) g_ctr = 0u;
}

// =================== EW = embedding @ Wi (+ bh folded for r,z) ===================
__global__ __launch_bounds__(256) void ew_kernel(const float* __restrict__ emb,
                                                 const float* __restrict__ Wi,
                                                 const float* __restrict__ bh) {
    __shared__ float semb[32][En];
    int vbase = blockIdx.y * 32;
    int cbase = blockIdx.x * 128;
    int tid = threadIdx.x;
    for (int i = tid; i < 32 * En / 4; i += 256)
        ((float4*)&semb[0][0])[i] = ((const float4*)(emb + (size_t)vbase * En))[i];
    __syncthreads();

    int cq = tid & 31;
    int vq = tid >> 5;
    int c  = cbase + cq * 4;
    int v0 = vq * 4;
    float acc[4][4];
    #pragma unroll
    for (int i = 0; i < 4; i++)
        #pragma unroll
        for (int j = 0; j < 4; j++) acc[i][j] = 0.0f;

    for (int e = 0; e < En; e++) {
        float4 w = *(const float4*)(Wi + (size_t)e * NG3 + c);
        #pragma unroll
        for (int vv = 0; vv < 4; vv++) {
            float a = semb[v0 + vv][e];
            acc[vv][0] = fmaf(a, w.x, acc[vv][0]);
            acc[vv][1] = fmaf(a, w.y, acc[vv][1]);
            acc[vv][2] = fmaf(a, w.z, acc[vv][2]);
            acc[vv][3] = fmaf(a, w.w, acc[vv][3]);
        }
    }
    float4 bb = make_float4(0.f, 0.f, 0.f, 0.f);
    if (c < 2 * Hn) bb = *(const float4*)(bh + c);
    #pragma unroll
    for (int vv = 0; vv < 4; vv++) {
        float4 o;
        o.x = acc[vv][0] + bb.x; o.y = acc[vv][1] + bb.y;
        o.z = acc[vv][2] + bb.z; o.w = acc[vv][3] + bb.w;
        *(float4*)(g_EW + (size_t)(vbase + v0 + vv) * NG3 + c) = o;
    }
}

// =================== persistent GRU recurrence (FFMA2 path) ===================
// 147 blocks x 256 threads. Block owns hidden cols [j0, j0+nj), nj<=7.
// SMEM: ws[1024][24] (Wh slice, k-major, col pairs interleaved, loaded ONCE)
//     + red: 256 thread-private chunks of 45 u64 (K-partial sums).
extern __shared__ float smem_gru[];

__global__ __launch_bounds__(256, 1) void gru_kernel(const int* __restrict__ tokens,
                                                     const float* __restrict__ Wh,
                                                     const float* __restrict__ bh) {
    float* ws = smem_gru;                         // ROWW * Hn floats (98304 B)
    u64*  red = (u64*)(smem_gru + ROWW * Hn);     // 256 * CHUNK u64   (92160 B)
    __shared__ int stok[Bn];

    int tid = threadIdx.x, bid = blockIdx.x;
    int j0 = bid * NJ;
    int nj = Hn - j0; if (nj > NJ) nj = NJ;
    if (nj < 0) nj = 0;

    // Load Wh slice once: ws[k][c], c = gate*7 + jj (cols 21..23 are zero pad).
    for (int idx = tid; idx < ROWW * Hn; idx += 256) {
        int k = idx / ROWW, c = idx - k * ROWW;
        float w = 0.0f;
        if (c < NCr) {
            int g = (c < 7) ? 0 : ((c < 14) ? 1 : 2);
            int jj = c - g * 7;
            if (jj < nj) w = Wh[(size_t)k * NG3 + g * Hn + j0 + jj];
        }
        ws[idx] = w;
    }
    __syncthreads();

    int bq = tid & 15, kq = tid >> 4;   // 16 b-groups x 16 k-groups
    int k0 = kq * 64;
    int bb = bq * 4;
    u64* redt = red + ((size_t)kq * 16 + bq) * CHUNK;

    for (int t = 0; t < Ln; t++) {
        const float* hbase = g_YH + (size_t)t * HB;

        // --- Phase A: partial GEMM over this thread's 64-k slice, f32x2 packed ---
        u64 acc[NCP][4];
        #pragma unroll
        for (int cp = 0; cp < NCP; cp++) {
            acc[cp][0] = 0ull; acc[cp][1] = 0ull; acc[cp][2] = 0ull; acc[cp][3] = 0ull;
        }

        float4 hc[4];
        #pragma unroll
        for (int k = 0; k < 4; k++)
            hc[k] = *(const float4*)(hbase + (size_t)(k0 + k) * Bn + bb);

        #pragma unroll 1
        for (int kk = 0; kk < 64; kk += 4) {
            // prefetch next k-quad (re-load current quad on last iter: harmless)
            int knext = (kk + 4 < 64) ? (kk + 4) : kk;
            float4 hn[4];
            #pragma unroll
            for (int k = 0; k < 4; k++)
                hn[k] = *(const float4*)(hbase + (size_t)(k0 + knext + k) * Bn + bb);

            #pragma unroll
            for (int k = 0; k < 4; k++) {
                const char* wrow = (const char*)(ws + (size_t)(k0 + kk + k) * ROWW);
                ulonglong2 w01 = *(const ulonglong2*)(wrow);
                ulonglong2 w23 = *(const ulonglong2*)(wrow + 16);
                ulonglong2 w45 = *(const ulonglong2*)(wrow + 32);
                ulonglong2 w67 = *(const ulonglong2*)(wrow + 48);
                ulonglong2 w89 = *(const ulonglong2*)(wrow + 64);
                u64       w10 = *(const u64*)(wrow + 80);
                u64 wp[NCP] = {w01.x, w01.y, w23.x, w23.y, w45.x, w45.y,
                               w67.x, w67.y, w89.x, w89.y, w10};
                u64 hh0 = pack2(hc[k].x);
                u64 hh1 = pack2(hc[k].y);
                u64 hh2 = pack2(hc[k].z);
                u64 hh3 = pack2(hc[k].w);
                #pragma unroll
                for (int cp = 0; cp < NCP; cp++) {
                    acc[cp][0] = fma2(wp[cp], hh0, acc[cp][0]);
                    acc[cp][1] = fma2(wp[cp], hh1, acc[cp][1]);
                    acc[cp][2] = fma2(wp[cp], hh2, acc[cp][2]);
                    acc[cp][3] = fma2(wp[cp], hh3, acc[cp][3]);
                }
            }
            #pragma unroll
            for (int k = 0; k < 4; k++) hc[k] = hn[k];
        }

        // --- Phase B: stash packed partials (thread-private chunk, bank-spread) ---
        #pragma unroll
        for (int i = 0; i < 4; i++)
            #pragma unroll
            for (int cp = 0; cp < NCP; cp++)
                redt[i * NCP + cp] = acc[cp][i];
        if (tid < Bn) stok[tid] = tokens[tid * Ln + t];
        __syncthreads();

        // --- Phase C: reduce 16 K-partials, apply gates, write h_{t+1} ---
        const float* rf = (const float*)red;
        for (int o = tid; o < Bn * NJ; o += 256) {
            int b = o & 63, jj = o >> 6;
            if (jj < nj) {
                int bq2 = b >> 2, i2 = b & 3;
                int c0 = jj, c1 = 7 + jj, c2 = 14 + jj;
                float s0 = 0.f, s1 = 0.f, s2 = 0.f;
                #pragma unroll
                for (int q = 0; q < 16; q++) {
                    const float* rp = rf + (((size_t)q * 16 + bq2) * CHUNK + (size_t)i2 * NCP) * 2;
                    s0 += rp[c0];
                    s1 += rp[c1];
                    s2 += rp[c2];
                }
                int j = j0 + jj;
                const float* ew = g_EW + (size_t)stok[b] * NG3;
                float xr = ew[j], xz = ew[Hn + j], xn = ew[2 * Hn + j];
                float r = 1.0f / (1.0f + __expf(-(xr + s0)));
                float z = 1.0f / (1.0f + __expf(-(xz + s1)));
                float hnl = s2 + bh[2 * Hn + j];
                float n = tanhf(xn + r * hnl);
                float hp = hbase[(size_t)j * Bn + b];
                float hnew = (1.0f - z) * n + z * hp;
                g_YH[(size_t)(t + 1) * HB + (size_t)j * Bn + b] = hnew;
            }
        }

        // --- grid barrier (counter-based) ---
        __syncthreads();
        if (tid == 0) {
            __threadfence();
            atomicAdd(&g_ctr, 1u);
            unsigned target = (unsigned)NB * (unsigned)(t + 1);
            while (*((volatile unsigned*)&g_ctr) < target) { }
        }
        __syncthreads();
    }
}

// =================== logits = Y @ Wout + bout (FFMA2) ===================
// grid (2, 256): block = one timestep x 128-v tile; 64b x 128v, K=1024
__global__ __launch_bounds__(256, 1) void out_kernel(const float* __restrict__ Wout,
                                                     const float* __restrict__ bout,
                                                     float* __restrict__ out) {
    __shared__ float sY[32 * Bn];     // [kk][b]
    __shared__ float sW[32 * 128];    // [kk][v]
    int t = blockIdx.y;
    int vbase = blockIdx.x * 128;
    int tid = threadIdx.x;
    int bq = tid & 15, vq = tid >> 4;
    int bb = bq * 4;
    int vv0 = vq * 8;
    const float* Yt = g_YH + (size_t)(t + 1) * HB;

    u64 acc2[4][4];
    #pragma unroll
    for (int i = 0; i < 4; i++)
        #pragma unroll
        for (int j = 0; j < 4; j++) acc2[i][j] = 0ull;

    for (int kc = 0; kc < Hn; kc += 32) {
        for (int i = tid; i < 32 * Bn / 4; i += 256)
            ((float4*)sY)[i] = ((const float4*)(Yt + (size_t)kc * Bn))[i];
        for (int i = tid; i < 32 * 128 / 4; i += 256) {
            int kk = i >> 5;
            int v4 = (i & 31) * 4;
            ((float4*)sW)[i] = *(const float4*)(Wout + (size_t)(kc + kk) * Vn + vbase + v4);
        }
        __syncthreads();
        #pragma unroll 4
        for (int kk = 0; kk < 32; kk++) {
            float4 y4 = *(const float4*)(sY + kk * Bn + bb);
            ulonglong2 wA = *(const ulonglong2*)(sW + kk * 128 + vv0);
            ulonglong2 wB = *(const ulonglong2*)(sW + kk * 128 + vv0 + 4);
            u64 wp[4] = {wA.x, wA.y, wB.x, wB.y};
            u64 yy[4] = {pack2(y4.x), pack2(y4.y), pack2(y4.z), pack2(y4.w)};
            #pragma unroll
            for (int i = 0; i < 4; i++)
                #pragma unroll
                for (int j = 0; j < 4; j++)
                    acc2[i][j] = fma2(yy[i], wp[j], acc2[i][j]);
        }
        __syncthreads();
    }

    float4 ba = *(const float4*)(bout + vbase + vv0);
    float4 bbv = *(const float4*)(bout + vbase + vv0 + 4);
    float bsum[8] = {ba.x, ba.y, ba.z, ba.w, bbv.x, bbv.y, bbv.z, bbv.w};
    #pragma unroll
    for (int i = 0; i < 4; i++) {
        float vals[8];
        #pragma unroll
        for (int j = 0; j < 4; j++) {
            unsigned lo, hi;
            asm("mov.b64 {%0, %1}, %2;" : "=r"(lo), "=r"(hi) : "l"(acc2[i][j]));
            vals[2 * j]     = __uint_as_float(lo);
            vals[2 * j + 1] = __uint_as_float(hi);
        }
        float* po = out + (size_t)(bb + i) * Ln * Vn + (size_t)t * Vn + vbase + vv0;
        float4 o0, o1;
        o0.x = vals[0] + bsum[0]; o0.y = vals[1] + bsum[1];
        o0.z = vals[2] + bsum[2]; o0.w = vals[3] + bsum[3];
        o1.x = vals[4] + bsum[4]; o1.y = vals[5] + bsum[5];
        o1.z = vals[6] + bsum[6]; o1.w = vals[7] + bsum[7];
        *(float4*)(po + 0) = o0;
        *(float4*)(po + 4) = o1;
    }
}

// =================== launch ===================
extern "C" void kernel_launch(void* const* d_in, const int* in_sizes, int n_in,
                              void* d_out, int out_size) {
    const int*   tokens = (const int*)d_in[0];
    const float* emb    = (const float*)d_in[1];
    const float* Wi     = (const float*)d_in[2];
    const float* Wh     = (const float*)d_in[3];
    const float* bh     = (const float*)d_in[4];
    const float* Wout   = (const float*)d_in[5];
    const float* bout   = (const float*)d_in[6];
    float* out = (float*)d_out;

    const int smem_bytes = ROWW * Hn * (int)sizeof(float) + 256 * CHUNK * (int)sizeof(u64);
    cudaFuncSetAttribute(gru_kernel, cudaFuncAttributeMaxDynamicSharedMemorySize, smem_bytes);

    reset_kernel<<<32, 256>>>();
    ew_kernel<<<dim3(24, 8), 256>>>(emb, Wi, bh);
    gru_kernel<<<NB, 256, smem_bytes>>>(tokens, Wh, bh);
    out_kernel<<<dim3(2, 256), 256>>>(Wout, bout, out);
}